// round 14
// baseline (speedup 1.0000x reference)
#include <cuda_runtime.h>
#include <cuda_bf16.h>

#define NN 50000
#define EE 800000
#define EP (EE + NN)      // edges + self loops = 850000
#define FIN 64
#define FOUT 256          // HEADS*HID
#define NC 16
#define SCAN_B 512
#define SCAN_NB ((NN + SCAN_B - 1) / SCAN_B)   // 98

// ---------------- scratch (device globals; no allocations allowed) --------
__device__ float4 g_y[NN * 64];       // [N,256] aggregated x per head (h-major)
__device__ float4 g_xh2[NN * 4];      // [N,16]  layer2 features
__device__ float4 g_a_src1[NN];       // [N,4]
__device__ float4 g_a_dst1[NN];       // [N,4]
__device__ float4 g_alpha[EP];        // per-edge unnormalized weights (CSR order)
__device__ float4 g_den[NN];          // per-node softmax denominators (atomic)
__device__ float  g_ws1[FOUT];        // W1_h @ att_src_h, [4][64]
__device__ float  g_wd1[FOUT];        // W1_h @ att_dst_h, [4][64]
__device__ float  g_a_src2[NN];
__device__ float  g_a_dst2[NN];
__device__ int    g_rowptr[NN + 1];
__device__ int    g_cnt[NN];
__device__ int    g_cur[NN];
__device__ int    g_col[EP];          // CSR: src node per incoming edge of dst
__device__ int    g_is64 = 1;         // static init; detect only ever clears -> deterministic
__device__ int    g_bsum[SCAN_NB];
__device__ int    g_boff[SCAN_NB];
__device__ unsigned g_scan_ctr;

// ---------------- helpers -------------------------------------------------
__device__ __forceinline__ float wsum(float v) {
#pragma unroll
    for (int o = 16; o; o >>= 1) v += __shfl_xor_sync(0xffffffffu, v, o);
    return v;
}
__device__ __forceinline__ float lrelu(float e) { return e > 0.f ? e : 0.2f * e; }

__device__ __forceinline__ int clampN(int v) {
    return v < 0 ? 0 : (v >= NN ? NN - 1 : v);
}

__device__ __forceinline__ int edge_at(const void* ei, int i) {
    if (g_is64) return (int)((const long long*)ei)[i];
    return ((const int*)ei)[i];
}

__device__ __forceinline__ void xadd16(float4& a0, float4& a1, float4& a2, float4& a3) {
    a0.x += __shfl_xor_sync(0xffffffffu, a0.x, 16);
    a0.y += __shfl_xor_sync(0xffffffffu, a0.y, 16);
    a0.z += __shfl_xor_sync(0xffffffffu, a0.z, 16);
    a0.w += __shfl_xor_sync(0xffffffffu, a0.w, 16);
    a1.x += __shfl_xor_sync(0xffffffffu, a1.x, 16);
    a1.y += __shfl_xor_sync(0xffffffffu, a1.y, 16);
    a1.z += __shfl_xor_sync(0xffffffffu, a1.z, 16);
    a1.w += __shfl_xor_sync(0xffffffffu, a1.w, 16);
    a2.x += __shfl_xor_sync(0xffffffffu, a2.x, 16);
    a2.y += __shfl_xor_sync(0xffffffffu, a2.y, 16);
    a2.z += __shfl_xor_sync(0xffffffffu, a2.z, 16);
    a2.w += __shfl_xor_sync(0xffffffffu, a2.w, 16);
    a3.x += __shfl_xor_sync(0xffffffffu, a3.x, 16);
    a3.y += __shfl_xor_sync(0xffffffffu, a3.y, 16);
    a3.z += __shfl_xor_sync(0xffffffffu, a3.z, 16);
    a3.w += __shfl_xor_sync(0xffffffffu, a3.w, 16);
}

// ---------------- zero + dtype detect (merged) ----------------------------
__global__ void k_zero(const long long* __restrict__ ei) {
    int i = blockIdx.x * blockDim.x + threadIdx.x;
    if (i == 0) g_scan_ctr = 0;
    if (i < 1024) {
        long long v = ei[i];
        if (v < 0 || v >= NN) g_is64 = 0;
    }
    if (i < NN) {
        g_cnt[i] = 0;
        g_cur[i] = 0;
        g_den[i] = make_float4(0.f, 0.f, 0.f, 0.f);
    }
}

// ---------------- CSR build -----------------------------------------------
__global__ void k_count(const void* __restrict__ ei) {
    int i = blockIdx.x * blockDim.x + threadIdx.x;
    if (i >= EP) return;
    int d = (i < EE) ? clampN(edge_at(ei, EE + i)) : (i - EE);
    atomicAdd(&g_cnt[d], 1);
}

__global__ void k_scan1() {
    __shared__ int sh[SCAN_B];
    __shared__ int lastFlag;
    int t = threadIdx.x, b = blockIdx.x;
    int i = b * SCAN_B + t;
    int v = (i < NN) ? g_cnt[i] : 0;
    sh[t] = v; __syncthreads();
#pragma unroll
    for (int off = 1; off < SCAN_B; off <<= 1) {
        int tv = (t >= off) ? sh[t - off] : 0;
        __syncthreads();
        sh[t] += tv;
        __syncthreads();
    }
    if (i < NN) g_rowptr[i + 1] = sh[t];
    if (t == SCAN_B - 1) g_bsum[b] = sh[t];
    __threadfence();
    __syncthreads();
    if (t == 0) {
        unsigned old = atomicAdd(&g_scan_ctr, 1u);
        lastFlag = (old == gridDim.x - 1);
    }
    __syncthreads();
    if (lastFlag && t == 0) {
        int run = 0;
        for (int j = 0; j < SCAN_NB; j++) { g_boff[j] = run; run += g_bsum[j]; }
    }
}

__global__ void k_scan3() {
    int t = threadIdx.x, b = blockIdx.x;
    int i = b * SCAN_B + t;
    if (i < NN) g_rowptr[i + 1] += g_boff[b];
    if (i == 0) g_rowptr[0] = 0;
}

// CSR scatter + per-edge weight + denominator accumulation (needs a_src1/dst1)
__global__ void k_fill(const void* __restrict__ ei) {
    int i = blockIdx.x * blockDim.x + threadIdx.x;
    if (i >= EP) return;
    int s, d;
    if (i < EE) { s = clampN(edge_at(ei, i)); d = clampN(edge_at(ei, EE + i)); }
    else        { s = i - EE;                 d = i - EE; }
    int pos = g_rowptr[d] + atomicAdd(&g_cur[d], 1);
    g_col[pos] = s;
    float4 av = g_a_src1[s];
    float4 dv = g_a_dst1[d];
    float4 p;
    p.x = __expf(lrelu(av.x + dv.x));
    p.y = __expf(lrelu(av.y + dv.y));
    p.z = __expf(lrelu(av.z + dv.z));
    p.w = __expf(lrelu(av.w + dv.w));
    g_alpha[pos] = p;
    float* den = (float*)g_den + 4 * d;
    atomicAdd(den + 0, p.x);
    atomicAdd(den + 1, p.y);
    atomicAdd(den + 2, p.z);
    atomicAdd(den + 3, p.w);
}

// ---------------- fold W1 into attention vectors --------------------------
__global__ void k_wvec(const float* __restrict__ W1,
                       const float* __restrict__ as1, const float* __restrict__ ad1) {
    int t = threadIdx.x;          // t = h*64 + k
    int h = t >> 6, kk = t & 63;
    float s = 0.f, d = 0.f;
#pragma unroll
    for (int j = 0; j < 64; j++) {
        float w = W1[kk * FOUT + h * 64 + j];
        s += w * as1[h * 64 + j];
        d += w * ad1[h * 64 + j];
    }
    g_ws1[t] = s;
    g_wd1[t] = d;
}

// ---------------- attention scalars from x directly -----------------------
__global__ void k_attsc(const float* __restrict__ x) {
    __shared__ float ws[FOUT], wd[FOUT];
    int t = threadIdx.x;
    if (t < FOUT) { ws[t] = g_ws1[t]; wd[t] = g_wd1[t]; }
    __syncthreads();
    int warp = (blockIdx.x * blockDim.x + threadIdx.x) >> 5;
    int lane = threadIdx.x & 31;
    if (warp >= NN) return;
    float2 xv = ((const float2*)(x + warp * 64))[lane];
    float s[4], d[4];
#pragma unroll
    for (int h = 0; h < 4; h++) {
        float ps = xv.x * ws[h * 64 + 2 * lane] + xv.y * ws[h * 64 + 2 * lane + 1];
        float pd = xv.x * wd[h * 64 + 2 * lane] + xv.y * wd[h * 64 + 2 * lane + 1];
        s[h] = wsum(ps);
        d[h] = wsum(pd);
    }
    if (lane == 0) {
        g_a_src1[warp] = make_float4(s[0], s[1], s[2], s[3]);
        g_a_dst1[warp] = make_float4(d[0], d[1], d[2], d[3]);
    }
}

// ---------------- layer 1 aggregation: SINGLE x-gather sweep --------------
// warp per dst node; weights read sequentially from g_alpha (CSR order),
// denominators from g_den. Half-warp edge split; merge via shfl(16).
__global__ void k_l1edge(const float* __restrict__ x) {
    int warp = (blockIdx.x * blockDim.x + threadIdx.x) >> 5;
    int lane = threadIdx.x & 31;
    if (warp >= NN) return;
    int d = warp;
    int beg = g_rowptr[d], end = g_rowptr[d + 1];
    float4 dv = g_den[d];
    float i0 = 1.f / (dv.x + 1e-16f), i1 = 1.f / (dv.y + 1e-16f);
    float i2 = 1.f / (dv.z + 1e-16f), i3 = 1.f / (dv.w + 1e-16f);

    int half = lane >> 4;        // 0: even edge offsets, 1: odd
    int l16  = lane & 15;
    float4 a0 = {0,0,0,0}, a1 = {0,0,0,0}, a2 = {0,0,0,0}, a3 = {0,0,0,0};
    float4 b0 = {0,0,0,0}, b1 = {0,0,0,0}, b2 = {0,0,0,0}, b3 = {0,0,0,0};
    int k = beg + half;
    for (; k + 2 < end; k += 4) {           // 2 edges per half per iter
        float4 p0 = g_alpha[k];
        float4 p1 = g_alpha[k + 2];
        int n0 = g_col[k], n1 = g_col[k + 2];
        float4 x0 = ((const float4*)(x + n0 * 64))[l16];
        float4 x1 = ((const float4*)(x + n1 * 64))[l16];
        a0.x += p0.x * x0.x; a0.y += p0.x * x0.y; a0.z += p0.x * x0.z; a0.w += p0.x * x0.w;
        a1.x += p0.y * x0.x; a1.y += p0.y * x0.y; a1.z += p0.y * x0.z; a1.w += p0.y * x0.w;
        a2.x += p0.z * x0.x; a2.y += p0.z * x0.y; a2.z += p0.z * x0.z; a2.w += p0.z * x0.w;
        a3.x += p0.w * x0.x; a3.y += p0.w * x0.y; a3.z += p0.w * x0.z; a3.w += p0.w * x0.w;
        b0.x += p1.x * x1.x; b0.y += p1.x * x1.y; b0.z += p1.x * x1.z; b0.w += p1.x * x1.w;
        b1.x += p1.y * x1.x; b1.y += p1.y * x1.y; b1.z += p1.y * x1.z; b1.w += p1.y * x1.w;
        b2.x += p1.z * x1.x; b2.y += p1.z * x1.y; b2.z += p1.z * x1.z; b2.w += p1.z * x1.w;
        b3.x += p1.w * x1.x; b3.y += p1.w * x1.y; b3.z += p1.w * x1.z; b3.w += p1.w * x1.w;
    }
    if (k < end) {                           // tail edge for this half
        float4 p0 = g_alpha[k];
        int n0 = g_col[k];
        float4 x0 = ((const float4*)(x + n0 * 64))[l16];
        a0.x += p0.x * x0.x; a0.y += p0.x * x0.y; a0.z += p0.x * x0.z; a0.w += p0.x * x0.w;
        a1.x += p0.y * x0.x; a1.y += p0.y * x0.y; a1.z += p0.y * x0.z; a1.w += p0.y * x0.w;
        a2.x += p0.z * x0.x; a2.y += p0.z * x0.y; a2.z += p0.z * x0.z; a2.w += p0.z * x0.w;
        a3.x += p0.w * x0.x; a3.y += p0.w * x0.y; a3.z += p0.w * x0.z; a3.w += p0.w * x0.w;
    }
    a0.x += b0.x; a0.y += b0.y; a0.z += b0.z; a0.w += b0.w;
    a1.x += b1.x; a1.y += b1.y; a1.z += b1.z; a1.w += b1.w;
    a2.x += b2.x; a2.y += b2.y; a2.z += b2.z; a2.w += b2.w;
    a3.x += b3.x; a3.y += b3.y; a3.z += b3.z; a3.w += b3.w;
    xadd16(a0, a1, a2, a3);
    if (half == 0) {
        a0.x *= i0; a0.y *= i0; a0.z *= i0; a0.w *= i0;
        a1.x *= i1; a1.y *= i1; a1.z *= i1; a1.w *= i1;
        a2.x *= i2; a2.y *= i2; a2.z *= i2; a2.w *= i2;
        a3.x *= i3; a3.y *= i3; a3.z *= i3; a3.w *= i3;
        float4* yr = (float4*)((float*)g_y + d * 256);
        yr[l16]      = a0;
        yr[16 + l16] = a1;
        yr[32 + l16] = a2;
        yr[48 + l16] = a3;
    }
}

// ---------------- fused: out1 = y@blockdiag(W1); h=elu(+b1); xh2=h@W2 -----
__global__ void k_l2fused(const float* __restrict__ W1, const float* __restrict__ b1,
                          const float* __restrict__ W2,
                          const float* __restrict__ as2, const float* __restrict__ ad2) {
    __shared__ float4 buf4[16][64];        // y tile, later h tile  (16KB)
    __shared__ float  W2s[FOUT * NC];      // W2 as-is              (16KB)
    __shared__ float  xs2[16][NC + 1];
    __shared__ float  a2s[NC], a2d[NC];
    int t = threadIdx.x;                   // 256 threads
    for (int i = t; i < FOUT * NC; i += 256) W2s[i] = W2[i];
    if (t < NC) { a2s[t] = as2[t]; a2d[t] = ad2[t]; }
    int row0 = blockIdx.x * 16;
    for (int i = t; i < 16 * 64; i += 256) {
        int r = i >> 6, c = i & 63;
        int gr = row0 + r;
        buf4[r][c] = (gr < NN) ? g_y[gr * 64 + c] : make_float4(0.f, 0.f, 0.f, 0.f);
    }
    __syncthreads();
    int h = t >> 6;
    float acc[16];
#pragma unroll
    for (int r = 0; r < 16; r++) acc[r] = 0.f;
    int kbase = h * 16;
    for (int kk = 0; kk < 16; kk++) {
        int krow = kk * 4;
        float w0 = W1[(krow + 0) * FOUT + t];
        float w1 = W1[(krow + 1) * FOUT + t];
        float w2 = W1[(krow + 2) * FOUT + t];
        float w3 = W1[(krow + 3) * FOUT + t];
#pragma unroll
        for (int r = 0; r < 16; r++) {
            float4 yv = buf4[r][kbase + kk];
            acc[r] += yv.x * w0 + yv.y * w1 + yv.z * w2 + yv.w * w3;
        }
    }
    float bb = b1[t];
    __syncthreads();
    float* bufs = (float*)buf4;
#pragma unroll
    for (int r = 0; r < 16; r++) {
        float v = acc[r] + bb;
        bufs[r * 256 + t] = v > 0.f ? v : (__expf(v) - 1.f);
    }
    __syncthreads();
    int r2 = t >> 4, c2 = t & 15;
    int gr2 = row0 + r2;
    float a = 0.f;
    const float* hrow = bufs + r2 * 256;
#pragma unroll 8
    for (int k = 0; k < FOUT; k++) a += hrow[k] * W2s[k * NC + c2];
    if (gr2 < NN) ((float*)g_xh2)[gr2 * NC + c2] = a;
    xs2[r2][c2] = a;
    __syncthreads();
    if (c2 < 2 && gr2 < NN) {
        float s = 0.f;
#pragma unroll
        for (int j = 0; j < NC; j++) s += xs2[r2][j] * (c2 ? a2d[j] : a2s[j]);
        if (c2) g_a_dst2[gr2] = s; else g_a_src2[gr2] = s;
    }
}

// ---------------- layer 2 aggregation (plain exp) + log_softmax -----------
__global__ void k_agg2(const float* __restrict__ b2, float* __restrict__ out) {
    int warp = (blockIdx.x * blockDim.x + threadIdx.x) >> 5;
    int lane = threadIdx.x & 31;
    if (warp >= NN) return;
    int d = warp;
    int beg = g_rowptr[d], end = g_rowptr[d + 1];
    float adn = g_a_dst2[d];

    float ssum = 0.f;
    float acc[NC];
#pragma unroll
    for (int j = 0; j < NC; j++) acc[j] = 0.f;

    for (int k = beg + lane; k < end; k += 32) {
        int s = g_col[k];
        float p = __expf(lrelu(g_a_src2[s] + adn));
        ssum += p;
        const float4* xp = g_xh2 + s * 4;
        float4 v0 = xp[0], v1 = xp[1], v2 = xp[2], v3 = xp[3];
        acc[0] += v0.x * p;  acc[1] += v0.y * p;
        acc[2] += v0.z * p;  acc[3] += v0.w * p;
        acc[4] += v1.x * p;  acc[5] += v1.y * p;
        acc[6] += v1.z * p;  acc[7] += v1.w * p;
        acc[8] += v2.x * p;  acc[9] += v2.y * p;
        acc[10] += v2.z * p; acc[11] += v2.w * p;
        acc[12] += v3.x * p; acc[13] += v3.y * p;
        acc[14] += v3.z * p; acc[15] += v3.w * p;
    }
    ssum = wsum(ssum);
#pragma unroll
    for (int j = 0; j < NC; j++) acc[j] = wsum(acc[j]);
    float inv = 1.f / (ssum + 1e-16f);

    float l[NC];
    float mm = -1e30f;
#pragma unroll
    for (int j = 0; j < NC; j++) { l[j] = acc[j] * inv + b2[j]; mm = fmaxf(mm, l[j]); }
    float ls = 0.f;
#pragma unroll
    for (int j = 0; j < NC; j++) ls += __expf(l[j] - mm);
    ls = logf(ls) + mm;
    float v = l[0];
#pragma unroll
    for (int j = 1; j < NC; j++) if (lane == j) v = l[j];
    if (lane < NC) out[d * NC + lane] = v - ls;
}

// ---------------- launch ---------------------------------------------------
extern "C" void kernel_launch(void* const* d_in, const int* in_sizes, int n_in,
                              void* d_out, int out_size) {
    const float* x   = (const float*)d_in[0];
    const void*  ei  = d_in[1];
    const float* W1  = (const float*)d_in[2];
    const float* as1 = (const float*)d_in[3];
    const float* ad1 = (const float*)d_in[4];
    const float* b1  = (const float*)d_in[5];
    const float* W2  = (const float*)d_in[6];
    const float* as2 = (const float*)d_in[7];
    const float* ad2 = (const float*)d_in[8];
    const float* b2  = (const float*)d_in[9];
    float* out = (float*)d_out;

    static cudaStream_t s2 = nullptr;
    static cudaEvent_t evFork = nullptr, evJoin = nullptr;
    if (!s2) {
        cudaStreamCreateWithFlags(&s2, cudaStreamNonBlocking);
        cudaEventCreateWithFlags(&evFork, cudaEventDisableTiming);
        cudaEventCreateWithFlags(&evJoin, cudaEventDisableTiming);
    }

    // fork: independent weight/attention-scalar chain on s2
    cudaEventRecord(evFork, 0);
    cudaStreamWaitEvent(s2, evFork, 0);
    k_wvec <<<1, 256, 0, s2>>>(W1, as1, ad1);
    k_attsc<<<(NN + 7) / 8, 256, 0, s2>>>(x);
    cudaEventRecord(evJoin, s2);

    // main chain: CSR count/scan (independent of attention scalars)
    k_zero <<<(NN + 255) / 256, 256>>>((const long long*)ei);
    k_count<<<(EP + 255) / 256, 256>>>(ei);
    k_scan1<<<SCAN_NB, SCAN_B>>>();
    k_scan3<<<SCAN_NB, SCAN_B>>>();

    // join (k_fill needs a_src1/a_dst1), then scatter+weights and the rest
    cudaStreamWaitEvent(0, evJoin, 0);
    k_fill   <<<(EP + 255) / 256, 256>>>(ei);
    k_l1edge <<<(NN + 7) / 8, 256>>>(x);
    k_l2fused<<<(NN + 15) / 16, 256>>>(W1, b1, W2, as2, ad2);
    k_agg2   <<<(NN + 7) / 8, 256>>>(b2, out);
}

// round 15
// speedup vs baseline: 1.0947x; 1.0947x over previous
#include <cuda_runtime.h>
#include <cuda_bf16.h>
#include <cuda_fp16.h>

#define NN 50000
#define EE 800000
#define EP (EE + NN)      // edges + self loops = 850000
#define FIN 64
#define FOUT 256          // HEADS*HID
#define NC 16
#define SCAN_B 512
#define SCAN_NB ((NN + SCAN_B - 1) / SCAN_B)   // 98
#define SLOTS 128         // smem per-warp edge slots in k_l1edge

// ---------------- scratch (device globals; no allocations allowed) --------
__device__ float4  g_y[NN * 64];      // [N,256] aggregated x per head (h-major)
__device__ float4  g_xh2[NN * 4];     // [N,16]  layer2 features
__device__ float4  g_a_src1[NN];      // [N,4]
__device__ float4  g_a_dst1[NN];      // [N,4]
__device__ float4  g_alpha[EP];       // spill space for deg>SLOTS nodes
__device__ __half2 g_xhalf[NN * 32];  // fp16 copy of x, [N,64] (128B/row)
__device__ float   g_ws1[FOUT];       // W1_h @ att_src_h, [4][64]
__device__ float   g_wd1[FOUT];       // W1_h @ att_dst_h, [4][64]
__device__ float   g_a_src2[NN];
__device__ float   g_a_dst2[NN];
__device__ int     g_rowptr[NN + 1];
__device__ int     g_cnt[NN];
__device__ int     g_cur[NN];
__device__ int     g_col[EP];         // CSR: src node per incoming edge of dst
__device__ int     g_is64 = 1;        // static init; detect only ever clears -> deterministic
__device__ int     g_bsum[SCAN_NB];
__device__ int     g_boff[SCAN_NB];
__device__ unsigned g_scan_ctr;

// ---------------- helpers -------------------------------------------------
__device__ __forceinline__ float wsum(float v) {
#pragma unroll
    for (int o = 16; o; o >>= 1) v += __shfl_xor_sync(0xffffffffu, v, o);
    return v;
}
__device__ __forceinline__ float lrelu(float e) { return e > 0.f ? e : 0.2f * e; }

__device__ __forceinline__ int clampN(int v) {
    return v < 0 ? 0 : (v >= NN ? NN - 1 : v);
}

__device__ __forceinline__ int edge_at(const void* ei, int i) {
    if (g_is64) return (int)((const long long*)ei)[i];
    return ((const int*)ei)[i];
}

__device__ __forceinline__ void xadd16(float4& a0, float4& a1, float4& a2, float4& a3) {
    a0.x += __shfl_xor_sync(0xffffffffu, a0.x, 16);
    a0.y += __shfl_xor_sync(0xffffffffu, a0.y, 16);
    a0.z += __shfl_xor_sync(0xffffffffu, a0.z, 16);
    a0.w += __shfl_xor_sync(0xffffffffu, a0.w, 16);
    a1.x += __shfl_xor_sync(0xffffffffu, a1.x, 16);
    a1.y += __shfl_xor_sync(0xffffffffu, a1.y, 16);
    a1.z += __shfl_xor_sync(0xffffffffu, a1.z, 16);
    a1.w += __shfl_xor_sync(0xffffffffu, a1.w, 16);
    a2.x += __shfl_xor_sync(0xffffffffu, a2.x, 16);
    a2.y += __shfl_xor_sync(0xffffffffu, a2.y, 16);
    a2.z += __shfl_xor_sync(0xffffffffu, a2.z, 16);
    a2.w += __shfl_xor_sync(0xffffffffu, a2.w, 16);
    a3.x += __shfl_xor_sync(0xffffffffu, a3.x, 16);
    a3.y += __shfl_xor_sync(0xffffffffu, a3.y, 16);
    a3.z += __shfl_xor_sync(0xffffffffu, a3.z, 16);
    a3.w += __shfl_xor_sync(0xffffffffu, a3.w, 16);
}

// load 4 consecutive x values (elements 4*j..4*j+3 of row n) from fp16 copy
__device__ __forceinline__ float4 ldx_half(int n, int j) {
    uint2 v = ((const uint2*)(g_xhalf + n * 32))[j];
    __half2 h01 = *(__half2*)&v.x;
    __half2 h23 = *(__half2*)&v.y;
    float2 f01 = __half22float2(h01);
    float2 f23 = __half22float2(h23);
    return make_float4(f01.x, f01.y, f23.x, f23.y);
}

// ---------------- zero + dtype detect (merged) ----------------------------
__global__ void k_zero(const long long* __restrict__ ei) {
    int i = blockIdx.x * blockDim.x + threadIdx.x;
    if (i == 0) g_scan_ctr = 0;
    if (i < 1024) {
        long long v = ei[i];
        if (v < 0 || v >= NN) g_is64 = 0;
    }
    if (i < NN) { g_cnt[i] = 0; g_cur[i] = 0; }
}

// ---------------- CSR build -----------------------------------------------
__global__ void k_count(const void* __restrict__ ei) {
    int i = blockIdx.x * blockDim.x + threadIdx.x;
    if (i >= EP) return;
    int d = (i < EE) ? clampN(edge_at(ei, EE + i)) : (i - EE);
    atomicAdd(&g_cnt[d], 1);
}

__global__ void k_scan1() {
    __shared__ int sh[SCAN_B];
    __shared__ int lastFlag;
    int t = threadIdx.x, b = blockIdx.x;
    int i = b * SCAN_B + t;
    int v = (i < NN) ? g_cnt[i] : 0;
    sh[t] = v; __syncthreads();
#pragma unroll
    for (int off = 1; off < SCAN_B; off <<= 1) {
        int tv = (t >= off) ? sh[t - off] : 0;
        __syncthreads();
        sh[t] += tv;
        __syncthreads();
    }
    if (i < NN) g_rowptr[i + 1] = sh[t];
    if (t == SCAN_B - 1) g_bsum[b] = sh[t];
    __threadfence();
    __syncthreads();
    if (t == 0) {
        unsigned old = atomicAdd(&g_scan_ctr, 1u);
        lastFlag = (old == gridDim.x - 1);
    }
    __syncthreads();
    if (lastFlag && t == 0) {
        int run = 0;
        for (int j = 0; j < SCAN_NB; j++) { g_boff[j] = run; run += g_bsum[j]; }
    }
}

__global__ void k_scan3() {
    int t = threadIdx.x, b = blockIdx.x;
    int i = b * SCAN_B + t;
    if (i < NN) g_rowptr[i + 1] += g_boff[b];
    if (i == 0) g_rowptr[0] = 0;
}

__global__ void k_fill(const void* __restrict__ ei) {
    int i = blockIdx.x * blockDim.x + threadIdx.x;
    if (i >= EP) return;
    int s, d;
    if (i < EE) { s = clampN(edge_at(ei, i)); d = clampN(edge_at(ei, EE + i)); }
    else        { s = i - EE;                 d = i - EE; }
    int pos = g_rowptr[d] + atomicAdd(&g_cur[d], 1);
    g_col[pos] = s;
}

// ---------------- fold W1 into attention vectors --------------------------
__global__ void k_wvec(const float* __restrict__ W1,
                       const float* __restrict__ as1, const float* __restrict__ ad1) {
    int t = threadIdx.x;          // t = h*64 + k
    int h = t >> 6, kk = t & 63;
    float s = 0.f, d = 0.f;
#pragma unroll
    for (int j = 0; j < 64; j++) {
        float w = W1[kk * FOUT + h * 64 + j];
        s += w * as1[h * 64 + j];
        d += w * ad1[h * 64 + j];
    }
    g_ws1[t] = s;
    g_wd1[t] = d;
}

// ---------------- attention scalars + fp16 x copy -------------------------
__global__ void k_attsc(const float* __restrict__ x) {
    __shared__ float ws[FOUT], wd[FOUT];
    int t = threadIdx.x;
    if (t < FOUT) { ws[t] = g_ws1[t]; wd[t] = g_wd1[t]; }
    __syncthreads();
    int warp = (blockIdx.x * blockDim.x + threadIdx.x) >> 5;
    int lane = threadIdx.x & 31;
    if (warp >= NN) return;
    float2 xv = ((const float2*)(x + warp * 64))[lane];
    g_xhalf[warp * 32 + lane] = __floats2half2_rn(xv.x, xv.y);
    float s[4], d[4];
#pragma unroll
    for (int h = 0; h < 4; h++) {
        float ps = xv.x * ws[h * 64 + 2 * lane] + xv.y * ws[h * 64 + 2 * lane + 1];
        float pd = xv.x * wd[h * 64 + 2 * lane] + xv.y * wd[h * 64 + 2 * lane + 1];
        s[h] = wsum(ps);
        d[h] = wsum(pd);
    }
    if (lane == 0) {
        g_a_src1[warp] = make_float4(s[0], s[1], s[2], s[3]);
        g_a_dst1[warp] = make_float4(d[0], d[1], d[2], d[3]);
    }
}

// ---------------- layer 1 fused: softmax weights + x aggregation ----------
// warp per dst node. Sweep 1: p = exp(lrelu(logit)) (bounded, no max needed).
// Sweep 2: half-warp edge split, x gathered from the fp16 copy (128B/row).
__global__ void k_l1edge() {
    __shared__ float4 sp[8][SLOTS];    // 16 KB
    int wip = threadIdx.x >> 5;
    int warp = (blockIdx.x * blockDim.x + threadIdx.x) >> 5;
    int lane = threadIdx.x & 31;
    if (warp >= NN) return;
    int d = warp;
    int beg = g_rowptr[d], end = g_rowptr[d + 1];
    int deg = end - beg;
    float4 adv = g_a_dst1[d];

    // sweep 1: weights into slots, sum denominators
    float s0 = 0.f, s1 = 0.f, s2 = 0.f, s3 = 0.f;
    for (int k = beg + lane; k < end; k += 32) {
        float4 av = g_a_src1[g_col[k]];
        float4 p;
        p.x = __expf(lrelu(av.x + adv.x));
        p.y = __expf(lrelu(av.y + adv.y));
        p.z = __expf(lrelu(av.z + adv.z));
        p.w = __expf(lrelu(av.w + adv.w));
        int slot = k - beg;
        if (slot < SLOTS) sp[wip][slot] = p; else g_alpha[k] = p;
        s0 += p.x; s1 += p.y; s2 += p.z; s3 += p.w;
    }
    s0 = wsum(s0); s1 = wsum(s1); s2 = wsum(s2); s3 = wsum(s3);
    float i0 = 1.f / (s0 + 1e-16f), i1 = 1.f / (s1 + 1e-16f);
    float i2 = 1.f / (s2 + 1e-16f), i3 = 1.f / (s3 + 1e-16f);
    if (deg > SLOTS) __threadfence_block();
    __syncwarp();

    // sweep 2: half-warp split over edges; lane covers 4 x-values via fp16
    int half = lane >> 4;        // 0: even edge offsets, 1: odd
    int l16  = lane & 15;
    float4 a0 = {0,0,0,0}, a1 = {0,0,0,0}, a2 = {0,0,0,0}, a3 = {0,0,0,0};
    float4 b0 = {0,0,0,0}, b1 = {0,0,0,0}, b2 = {0,0,0,0}, b3 = {0,0,0,0};
    int k = beg + half;
    for (; k + 2 < end; k += 4) {           // 2 edges per half per iter
        int sl0 = k - beg, sl1 = sl0 + 2;
        float4 p0 = (sl0 < SLOTS) ? sp[wip][sl0] : g_alpha[k];
        float4 p1 = (sl1 < SLOTS) ? sp[wip][sl1] : g_alpha[k + 2];
        int n0 = g_col[k], n1 = g_col[k + 2];
        float4 x0 = ldx_half(n0, l16);
        float4 x1 = ldx_half(n1, l16);
        a0.x += p0.x * x0.x; a0.y += p0.x * x0.y; a0.z += p0.x * x0.z; a0.w += p0.x * x0.w;
        a1.x += p0.y * x0.x; a1.y += p0.y * x0.y; a1.z += p0.y * x0.z; a1.w += p0.y * x0.w;
        a2.x += p0.z * x0.x; a2.y += p0.z * x0.y; a2.z += p0.z * x0.z; a2.w += p0.z * x0.w;
        a3.x += p0.w * x0.x; a3.y += p0.w * x0.y; a3.z += p0.w * x0.z; a3.w += p0.w * x0.w;
        b0.x += p1.x * x1.x; b0.y += p1.x * x1.y; b0.z += p1.x * x1.z; b0.w += p1.x * x1.w;
        b1.x += p1.y * x1.x; b1.y += p1.y * x1.y; b1.z += p1.y * x1.z; b1.w += p1.y * x1.w;
        b2.x += p1.z * x1.x; b2.y += p1.z * x1.y; b2.z += p1.z * x1.z; b2.w += p1.z * x1.w;
        b3.x += p1.w * x1.x; b3.y += p1.w * x1.y; b3.z += p1.w * x1.z; b3.w += p1.w * x1.w;
    }
    if (k < end) {                           // tail edge for this half
        int sl0 = k - beg;
        float4 p0 = (sl0 < SLOTS) ? sp[wip][sl0] : g_alpha[k];
        int n0 = g_col[k];
        float4 x0 = ldx_half(n0, l16);
        a0.x += p0.x * x0.x; a0.y += p0.x * x0.y; a0.z += p0.x * x0.z; a0.w += p0.x * x0.w;
        a1.x += p0.y * x0.x; a1.y += p0.y * x0.y; a1.z += p0.y * x0.z; a1.w += p0.y * x0.w;
        a2.x += p0.z * x0.x; a2.y += p0.z * x0.y; a2.z += p0.z * x0.z; a2.w += p0.z * x0.w;
        a3.x += p0.w * x0.x; a3.y += p0.w * x0.y; a3.z += p0.w * x0.z; a3.w += p0.w * x0.w;
    }
    a0.x += b0.x; a0.y += b0.y; a0.z += b0.z; a0.w += b0.w;
    a1.x += b1.x; a1.y += b1.y; a1.z += b1.z; a1.w += b1.w;
    a2.x += b2.x; a2.y += b2.y; a2.z += b2.z; a2.w += b2.w;
    a3.x += b3.x; a3.y += b3.y; a3.z += b3.z; a3.w += b3.w;
    xadd16(a0, a1, a2, a3);
    if (half == 0) {
        a0.x *= i0; a0.y *= i0; a0.z *= i0; a0.w *= i0;
        a1.x *= i1; a1.y *= i1; a1.z *= i1; a1.w *= i1;
        a2.x *= i2; a2.y *= i2; a2.z *= i2; a2.w *= i2;
        a3.x *= i3; a3.y *= i3; a3.z *= i3; a3.w *= i3;
        float4* yr = (float4*)((float*)g_y + d * 256);
        yr[l16]      = a0;
        yr[16 + l16] = a1;
        yr[32 + l16] = a2;
        yr[48 + l16] = a3;
    }
}

// ---------------- fused: out1 = y@blockdiag(W1); h=elu(+b1); xh2=h@W2 -----
__global__ void k_l2fused(const float* __restrict__ W1, const float* __restrict__ b1,
                          const float* __restrict__ W2,
                          const float* __restrict__ as2, const float* __restrict__ ad2) {
    __shared__ float4 buf4[16][64];        // y tile, later h tile  (16KB)
    __shared__ float  W2s[FOUT * NC];      // W2 as-is              (16KB)
    __shared__ float  xs2[16][NC + 1];
    __shared__ float  a2s[NC], a2d[NC];
    int t = threadIdx.x;                   // 256 threads
    for (int i = t; i < FOUT * NC; i += 256) W2s[i] = W2[i];
    if (t < NC) { a2s[t] = as2[t]; a2d[t] = ad2[t]; }
    int row0 = blockIdx.x * 16;
    for (int i = t; i < 16 * 64; i += 256) {
        int r = i >> 6, c = i & 63;
        int gr = row0 + r;
        buf4[r][c] = (gr < NN) ? g_y[gr * 64 + c] : make_float4(0.f, 0.f, 0.f, 0.f);
    }
    __syncthreads();
    int h = t >> 6;
    float acc[16];
#pragma unroll
    for (int r = 0; r < 16; r++) acc[r] = 0.f;
    int kbase = h * 16;
    for (int kk = 0; kk < 16; kk++) {
        int krow = kk * 4;
        float w0 = W1[(krow + 0) * FOUT + t];
        float w1 = W1[(krow + 1) * FOUT + t];
        float w2 = W1[(krow + 2) * FOUT + t];
        float w3 = W1[(krow + 3) * FOUT + t];
#pragma unroll
        for (int r = 0; r < 16; r++) {
            float4 yv = buf4[r][kbase + kk];
            acc[r] += yv.x * w0 + yv.y * w1 + yv.z * w2 + yv.w * w3;
        }
    }
    float bb = b1[t];
    __syncthreads();
    float* bufs = (float*)buf4;
#pragma unroll
    for (int r = 0; r < 16; r++) {
        float v = acc[r] + bb;
        bufs[r * 256 + t] = v > 0.f ? v : (__expf(v) - 1.f);
    }
    __syncthreads();
    int r2 = t >> 4, c2 = t & 15;
    int gr2 = row0 + r2;
    float a = 0.f;
    const float* hrow = bufs + r2 * 256;
#pragma unroll 8
    for (int k = 0; k < FOUT; k++) a += hrow[k] * W2s[k * NC + c2];
    if (gr2 < NN) ((float*)g_xh2)[gr2 * NC + c2] = a;
    xs2[r2][c2] = a;
    __syncthreads();
    if (c2 < 2 && gr2 < NN) {
        float s = 0.f;
#pragma unroll
        for (int j = 0; j < NC; j++) s += xs2[r2][j] * (c2 ? a2d[j] : a2s[j]);
        if (c2) g_a_dst2[gr2] = s; else g_a_src2[gr2] = s;
    }
}

// ---------------- layer 2 aggregation (plain exp) + log_softmax -----------
__global__ void k_agg2(const float* __restrict__ b2, float* __restrict__ out) {
    int warp = (blockIdx.x * blockDim.x + threadIdx.x) >> 5;
    int lane = threadIdx.x & 31;
    if (warp >= NN) return;
    int d = warp;
    int beg = g_rowptr[d], end = g_rowptr[d + 1];
    float adn = g_a_dst2[d];

    float ssum = 0.f;
    float acc[NC];
#pragma unroll
    for (int j = 0; j < NC; j++) acc[j] = 0.f;

    for (int k = beg + lane; k < end; k += 32) {
        int s = g_col[k];
        float p = __expf(lrelu(g_a_src2[s] + adn));
        ssum += p;
        const float4* xp = g_xh2 + s * 4;
        float4 v0 = xp[0], v1 = xp[1], v2 = xp[2], v3 = xp[3];
        acc[0] += v0.x * p;  acc[1] += v0.y * p;
        acc[2] += v0.z * p;  acc[3] += v0.w * p;
        acc[4] += v1.x * p;  acc[5] += v1.y * p;
        acc[6] += v1.z * p;  acc[7] += v1.w * p;
        acc[8] += v2.x * p;  acc[9] += v2.y * p;
        acc[10] += v2.z * p; acc[11] += v2.w * p;
        acc[12] += v3.x * p; acc[13] += v3.y * p;
        acc[14] += v3.z * p; acc[15] += v3.w * p;
    }
    ssum = wsum(ssum);
#pragma unroll
    for (int j = 0; j < NC; j++) acc[j] = wsum(acc[j]);
    float inv = 1.f / (ssum + 1e-16f);

    float l[NC];
    float mm = -1e30f;
#pragma unroll
    for (int j = 0; j < NC; j++) { l[j] = acc[j] * inv + b2[j]; mm = fmaxf(mm, l[j]); }
    float ls = 0.f;
#pragma unroll
    for (int j = 0; j < NC; j++) ls += __expf(l[j] - mm);
    ls = logf(ls) + mm;
    float v = l[0];
#pragma unroll
    for (int j = 1; j < NC; j++) if (lane == j) v = l[j];
    if (lane < NC) out[d * NC + lane] = v - ls;
}

// ---------------- launch ---------------------------------------------------
extern "C" void kernel_launch(void* const* d_in, const int* in_sizes, int n_in,
                              void* d_out, int out_size) {
    const float* x   = (const float*)d_in[0];
    const void*  ei  = d_in[1];
    const float* W1  = (const float*)d_in[2];
    const float* as1 = (const float*)d_in[3];
    const float* ad1 = (const float*)d_in[4];
    const float* b1  = (const float*)d_in[5];
    const float* W2  = (const float*)d_in[6];
    const float* as2 = (const float*)d_in[7];
    const float* ad2 = (const float*)d_in[8];
    const float* b2  = (const float*)d_in[9];
    float* out = (float*)d_out;

    static cudaStream_t s2 = nullptr;
    static cudaEvent_t evFork = nullptr, evJoin = nullptr;
    if (!s2) {
        cudaStreamCreateWithFlags(&s2, cudaStreamNonBlocking);
        cudaEventCreateWithFlags(&evFork, cudaEventDisableTiming);
        cudaEventCreateWithFlags(&evJoin, cudaEventDisableTiming);
    }

    // fork: independent weight/attention-scalar chain on s2
    cudaEventRecord(evFork, 0);
    cudaStreamWaitEvent(s2, evFork, 0);
    k_wvec <<<1, 256, 0, s2>>>(W1, as1, ad1);
    k_attsc<<<(NN + 7) / 8, 256, 0, s2>>>(x);
    cudaEventRecord(evJoin, s2);

    // main chain: CSR build
    k_zero <<<(NN + 255) / 256, 256>>>((const long long*)ei);
    k_count<<<(EP + 255) / 256, 256>>>(ei);
    k_scan1<<<SCAN_NB, SCAN_B>>>();
    k_scan3<<<SCAN_NB, SCAN_B>>>();
    k_fill <<<(EP + 255) / 256, 256>>>(ei);

    // join, then fused edge phase + tail
    cudaStreamWaitEvent(0, evJoin, 0);
    k_l1edge <<<(NN + 7) / 8, 256>>>();
    k_l2fused<<<(NN + 15) / 16, 256>>>(W1, b1, W2, as2, ad2);
    k_agg2   <<<(NN + 7) / 8, 256>>>(b2, out);
}

// round 17
// speedup vs baseline: 1.1493x; 1.0498x over previous
#include <cuda_runtime.h>
#include <cuda_bf16.h>
#include <cuda_fp16.h>

#define NN 50000
#define EE 800000
#define EP (EE + NN)      // edges + self loops = 850000
#define FIN 64
#define FOUT 256          // HEADS*HID
#define NC 16
#define SCAN_B 512
#define SCAN_NB ((NN + SCAN_B - 1) / SCAN_B)   // 98
#define SLOTS 128         // smem per-warp edge slots in k_l1edge

// ---------------- scratch (device globals; no allocations allowed) --------
__device__ __half2 g_yh[NN * 128];    // [N,256] aggregated x per head, fp16
__device__ __half  g_xh2h[NN * 16];   // [N,16]  layer2 features, fp16
__device__ float4  g_a_src1[NN];      // [N,4]
__device__ float4  g_a_dst1[NN];      // [N,4]
__device__ float4  g_alpha[EP];       // spill space for deg>SLOTS nodes
__device__ __half2 g_xhalf[NN * 32];  // fp16 copy of x, [N,64] (128B/row)
__device__ float   g_ws1[FOUT];       // W1_h @ att_src_h, [4][64]
__device__ float   g_wd1[FOUT];       // W1_h @ att_dst_h, [4][64]
__device__ float   g_a_src2[NN];
__device__ float   g_a_dst2[NN];
__device__ int     g_rowptr[NN + 1];
__device__ int     g_cnt[NN];
__device__ int     g_cur[NN];
__device__ int     g_col[EP];         // CSR: src node per incoming edge of dst
__device__ int     g_is64 = 1;        // static init; detect only ever clears -> deterministic
__device__ int     g_bsum[SCAN_NB];
__device__ int     g_boff[SCAN_NB];
__device__ unsigned g_scan_ctr;

// ---------------- helpers -------------------------------------------------
__device__ __forceinline__ float wsum(float v) {
#pragma unroll
    for (int o = 16; o; o >>= 1) v += __shfl_xor_sync(0xffffffffu, v, o);
    return v;
}
__device__ __forceinline__ float lrelu(float e) { return e > 0.f ? e : 0.2f * e; }

__device__ __forceinline__ int clampN(int v) {
    return v < 0 ? 0 : (v >= NN ? NN - 1 : v);
}

__device__ __forceinline__ int edge_at(const void* ei, int i) {
    if (g_is64) return (int)((const long long*)ei)[i];
    return ((const int*)ei)[i];
}

__device__ __forceinline__ void xadd16(float4& a0, float4& a1, float4& a2, float4& a3) {
    a0.x += __shfl_xor_sync(0xffffffffu, a0.x, 16);
    a0.y += __shfl_xor_sync(0xffffffffu, a0.y, 16);
    a0.z += __shfl_xor_sync(0xffffffffu, a0.z, 16);
    a0.w += __shfl_xor_sync(0xffffffffu, a0.w, 16);
    a1.x += __shfl_xor_sync(0xffffffffu, a1.x, 16);
    a1.y += __shfl_xor_sync(0xffffffffu, a1.y, 16);
    a1.z += __shfl_xor_sync(0xffffffffu, a1.z, 16);
    a1.w += __shfl_xor_sync(0xffffffffu, a1.w, 16);
    a2.x += __shfl_xor_sync(0xffffffffu, a2.x, 16);
    a2.y += __shfl_xor_sync(0xffffffffu, a2.y, 16);
    a2.z += __shfl_xor_sync(0xffffffffu, a2.z, 16);
    a2.w += __shfl_xor_sync(0xffffffffu, a2.w, 16);
    a3.x += __shfl_xor_sync(0xffffffffu, a3.x, 16);
    a3.y += __shfl_xor_sync(0xffffffffu, a3.y, 16);
    a3.z += __shfl_xor_sync(0xffffffffu, a3.z, 16);
    a3.w += __shfl_xor_sync(0xffffffffu, a3.w, 16);
}

// load 4 consecutive x values (elements 4*j..4*j+3 of row n) from fp16 copy
__device__ __forceinline__ float4 ldx_half(int n, int j) {
    uint2 v = ((const uint2*)(g_xhalf + n * 32))[j];
    __half2 h01 = *(__half2*)&v.x;
    __half2 h23 = *(__half2*)&v.y;
    float2 f01 = __half22float2(h01);
    float2 f23 = __half22float2(h23);
    return make_float4(f01.x, f01.y, f23.x, f23.y);
}

__device__ __forceinline__ uint2 pack_h4(float4 v) {
    __half2 lo = __floats2half2_rn(v.x, v.y);
    __half2 hi = __floats2half2_rn(v.z, v.w);
    uint2 r;
    r.x = *(unsigned*)&lo;
    r.y = *(unsigned*)&hi;
    return r;
}
__device__ __forceinline__ float4 unpack_h4(uint2 v) {
    __half2 lo = *(__half2*)&v.x;
    __half2 hi = *(__half2*)&v.y;
    float2 f01 = __half22float2(lo);
    float2 f23 = __half22float2(hi);
    return make_float4(f01.x, f01.y, f23.x, f23.y);
}

// ---------------- zero + dtype detect (merged) ----------------------------
__global__ void k_zero(const long long* __restrict__ ei) {
    int i = blockIdx.x * blockDim.x + threadIdx.x;
    if (i == 0) g_scan_ctr = 0;
    if (i < 1024) {
        long long v = ei[i];
        if (v < 0 || v >= NN) g_is64 = 0;
    }
    if (i < NN) { g_cnt[i] = 0; g_cur[i] = 0; }
}

// ---------------- CSR build -----------------------------------------------
__global__ void k_count(const void* __restrict__ ei) {
    int i = blockIdx.x * blockDim.x + threadIdx.x;
    if (i >= EP) return;
    int d = (i < EE) ? clampN(edge_at(ei, EE + i)) : (i - EE);
    atomicAdd(&g_cnt[d], 1);
}

__global__ void k_scan1() {
    __shared__ int sh[SCAN_B];
    __shared__ int lastFlag;
    int t = threadIdx.x, b = blockIdx.x;
    int i = b * SCAN_B + t;
    int v = (i < NN) ? g_cnt[i] : 0;
    sh[t] = v; __syncthreads();
#pragma unroll
    for (int off = 1; off < SCAN_B; off <<= 1) {
        int tv = (t >= off) ? sh[t - off] : 0;
        __syncthreads();
        sh[t] += tv;
        __syncthreads();
    }
    if (i < NN) g_rowptr[i + 1] = sh[t];
    if (t == SCAN_B - 1) g_bsum[b] = sh[t];
    __threadfence();
    __syncthreads();
    if (t == 0) {
        unsigned old = atomicAdd(&g_scan_ctr, 1u);
        lastFlag = (old == gridDim.x - 1);
    }
    __syncthreads();
    if (lastFlag && t == 0) {
        int run = 0;
        for (int j = 0; j < SCAN_NB; j++) { g_boff[j] = run; run += g_bsum[j]; }
    }
}

__global__ void k_scan3() {
    int t = threadIdx.x, b = blockIdx.x;
    int i = b * SCAN_B + t;
    if (i < NN) g_rowptr[i + 1] += g_boff[b];
    if (i == 0) g_rowptr[0] = 0;
}

__global__ void k_fill(const void* __restrict__ ei) {
    int i = blockIdx.x * blockDim.x + threadIdx.x;
    if (i >= EP) return;
    int s, d;
    if (i < EE) { s = clampN(edge_at(ei, i)); d = clampN(edge_at(ei, EE + i)); }
    else        { s = i - EE;                 d = i - EE; }
    int pos = g_rowptr[d] + atomicAdd(&g_cur[d], 1);
    g_col[pos] = s;
}

// ---------------- fold W1 into attention vectors --------------------------
__global__ void k_wvec(const float* __restrict__ W1,
                       const float* __restrict__ as1, const float* __restrict__ ad1) {
    int t = threadIdx.x;          // t = h*64 + k
    int h = t >> 6, kk = t & 63;
    float s = 0.f, d = 0.f;
#pragma unroll
    for (int j = 0; j < 64; j++) {
        float w = W1[kk * FOUT + h * 64 + j];
        s += w * as1[h * 64 + j];
        d += w * ad1[h * 64 + j];
    }
    g_ws1[t] = s;
    g_wd1[t] = d;
}

// ---------------- attention scalars + fp16 x copy -------------------------
__global__ void k_attsc(const float* __restrict__ x) {
    __shared__ float ws[FOUT], wd[FOUT];
    int t = threadIdx.x;
    if (t < FOUT) { ws[t] = g_ws1[t]; wd[t] = g_wd1[t]; }
    __syncthreads();
    int warp = (blockIdx.x * blockDim.x + threadIdx.x) >> 5;
    int lane = threadIdx.x & 31;
    if (warp >= NN) return;
    float2 xv = ((const float2*)(x + warp * 64))[lane];
    g_xhalf[warp * 32 + lane] = __floats2half2_rn(xv.x, xv.y);
    float s[4], d[4];
#pragma unroll
    for (int h = 0; h < 4; h++) {
        float ps = xv.x * ws[h * 64 + 2 * lane] + xv.y * ws[h * 64 + 2 * lane + 1];
        float pd = xv.x * wd[h * 64 + 2 * lane] + xv.y * wd[h * 64 + 2 * lane + 1];
        s[h] = wsum(ps);
        d[h] = wsum(pd);
    }
    if (lane == 0) {
        g_a_src1[warp] = make_float4(s[0], s[1], s[2], s[3]);
        g_a_dst1[warp] = make_float4(d[0], d[1], d[2], d[3]);
    }
}

// ---------------- layer 1 fused: softmax weights + x aggregation ----------
__global__ void k_l1edge() {
    __shared__ float4 sp[8][SLOTS];    // 16 KB
    int wip = threadIdx.x >> 5;
    int warp = (blockIdx.x * blockDim.x + threadIdx.x) >> 5;
    int lane = threadIdx.x & 31;
    if (warp >= NN) return;
    int d = warp;
    int beg = g_rowptr[d], end = g_rowptr[d + 1];
    int deg = end - beg;
    float4 adv = g_a_dst1[d];

    // sweep 1: weights into slots, sum denominators
    float s0 = 0.f, s1 = 0.f, s2 = 0.f, s3 = 0.f;
    for (int k = beg + lane; k < end; k += 32) {
        float4 av = g_a_src1[g_col[k]];
        float4 p;
        p.x = __expf(lrelu(av.x + adv.x));
        p.y = __expf(lrelu(av.y + adv.y));
        p.z = __expf(lrelu(av.z + adv.z));
        p.w = __expf(lrelu(av.w + adv.w));
        int slot = k - beg;
        if (slot < SLOTS) sp[wip][slot] = p; else g_alpha[k] = p;
        s0 += p.x; s1 += p.y; s2 += p.z; s3 += p.w;
    }
    s0 = wsum(s0); s1 = wsum(s1); s2 = wsum(s2); s3 = wsum(s3);
    float i0 = 1.f / (s0 + 1e-16f), i1 = 1.f / (s1 + 1e-16f);
    float i2 = 1.f / (s2 + 1e-16f), i3 = 1.f / (s3 + 1e-16f);
    if (deg > SLOTS) __threadfence_block();
    __syncwarp();

    // sweep 2: half-warp split over edges; lane covers 4 x-values via fp16
    int half = lane >> 4;        // 0: even edge offsets, 1: odd
    int l16  = lane & 15;
    float4 a0 = {0,0,0,0}, a1 = {0,0,0,0}, a2 = {0,0,0,0}, a3 = {0,0,0,0};
    float4 b0 = {0,0,0,0}, b1 = {0,0,0,0}, b2 = {0,0,0,0}, b3 = {0,0,0,0};
    int k = beg + half;
    for (; k + 2 < end; k += 4) {           // 2 edges per half per iter
        int sl0 = k - beg, sl1 = sl0 + 2;
        float4 p0 = (sl0 < SLOTS) ? sp[wip][sl0] : g_alpha[k];
        float4 p1 = (sl1 < SLOTS) ? sp[wip][sl1] : g_alpha[k + 2];
        int n0 = g_col[k], n1 = g_col[k + 2];
        float4 x0 = ldx_half(n0, l16);
        float4 x1 = ldx_half(n1, l16);
        a0.x += p0.x * x0.x; a0.y += p0.x * x0.y; a0.z += p0.x * x0.z; a0.w += p0.x * x0.w;
        a1.x += p0.y * x0.x; a1.y += p0.y * x0.y; a1.z += p0.y * x0.z; a1.w += p0.y * x0.w;
        a2.x += p0.z * x0.x; a2.y += p0.z * x0.y; a2.z += p0.z * x0.z; a2.w += p0.z * x0.w;
        a3.x += p0.w * x0.x; a3.y += p0.w * x0.y; a3.z += p0.w * x0.z; a3.w += p0.w * x0.w;
        b0.x += p1.x * x1.x; b0.y += p1.x * x1.y; b0.z += p1.x * x1.z; b0.w += p1.x * x1.w;
        b1.x += p1.y * x1.x; b1.y += p1.y * x1.y; b1.z += p1.y * x1.z; b1.w += p1.y * x1.w;
        b2.x += p1.z * x1.x; b2.y += p1.z * x1.y; b2.z += p1.z * x1.z; b2.w += p1.z * x1.w;
        b3.x += p1.w * x1.x; b3.y += p1.w * x1.y; b3.z += p1.w * x1.z; b3.w += p1.w * x1.w;
    }
    if (k < end) {                           // tail edge for this half
        int sl0 = k - beg;
        float4 p0 = (sl0 < SLOTS) ? sp[wip][sl0] : g_alpha[k];
        int n0 = g_col[k];
        float4 x0 = ldx_half(n0, l16);
        a0.x += p0.x * x0.x; a0.y += p0.x * x0.y; a0.z += p0.x * x0.z; a0.w += p0.x * x0.w;
        a1.x += p0.y * x0.x; a1.y += p0.y * x0.y; a1.z += p0.y * x0.z; a1.w += p0.y * x0.w;
        a2.x += p0.z * x0.x; a2.y += p0.z * x0.y; a2.z += p0.z * x0.z; a2.w += p0.z * x0.w;
        a3.x += p0.w * x0.x; a3.y += p0.w * x0.y; a3.z += p0.w * x0.z; a3.w += p0.w * x0.w;
    }
    a0.x += b0.x; a0.y += b0.y; a0.z += b0.z; a0.w += b0.w;
    a1.x += b1.x; a1.y += b1.y; a1.z += b1.z; a1.w += b1.w;
    a2.x += b2.x; a2.y += b2.y; a2.z += b2.z; a2.w += b2.w;
    a3.x += b3.x; a3.y += b3.y; a3.z += b3.z; a3.w += b3.w;
    xadd16(a0, a1, a2, a3);
    if (half == 0) {
        a0.x *= i0; a0.y *= i0; a0.z *= i0; a0.w *= i0;
        a1.x *= i1; a1.y *= i1; a1.z *= i1; a1.w *= i1;
        a2.x *= i2; a2.y *= i2; a2.z *= i2; a2.w *= i2;
        a3.x *= i3; a3.y *= i3; a3.z *= i3; a3.w *= i3;
        uint2* yr = (uint2*)(g_yh + d * 128);    // 64 uint2 per row
        yr[l16]      = pack_h4(a0);
        yr[16 + l16] = pack_h4(a1);
        yr[32 + l16] = pack_h4(a2);
        yr[48 + l16] = pack_h4(a3);
    }
}

// ---------------- fused: out1 = y@blockdiag(W1); h=elu(+b1); xh2=h@W2 -----
__global__ void k_l2fused(const float* __restrict__ W1, const float* __restrict__ b1,
                          const float* __restrict__ W2,
                          const float* __restrict__ as2, const float* __restrict__ ad2) {
    __shared__ float4 buf4[16][64];        // y tile, later h tile  (16KB)
    __shared__ float  W2s[FOUT * NC];      // W2 as-is              (16KB)
    __shared__ float  xs2[16][NC + 1];
    __shared__ float  a2s[NC], a2d[NC];
    int t = threadIdx.x;                   // 256 threads
    for (int i = t; i < FOUT * NC; i += 256) W2s[i] = W2[i];
    if (t < NC) { a2s[t] = as2[t]; a2d[t] = ad2[t]; }
    int row0 = blockIdx.x * 16;
    for (int i = t; i < 16 * 64; i += 256) {
        int r = i >> 6, c = i & 63;
        int gr = row0 + r;
        if (gr < NN) {
            uint2 v = ((const uint2*)(g_yh + gr * 128))[c];
            buf4[r][c] = unpack_h4(v);
        } else {
            buf4[r][c] = make_float4(0.f, 0.f, 0.f, 0.f);
        }
    }
    __syncthreads();
    int h = t >> 6;
    float acc[16];
#pragma unroll
    for (int r = 0; r < 16; r++) acc[r] = 0.f;
    int kbase = h * 16;
    for (int kk = 0; kk < 16; kk++) {
        int krow = kk * 4;
        float w0 = W1[(krow + 0) * FOUT + t];
        float w1 = W1[(krow + 1) * FOUT + t];
        float w2 = W1[(krow + 2) * FOUT + t];
        float w3 = W1[(krow + 3) * FOUT + t];
#pragma unroll
        for (int r = 0; r < 16; r++) {
            float4 yv = buf4[r][kbase + kk];
            acc[r] += yv.x * w0 + yv.y * w1 + yv.z * w2 + yv.w * w3;
        }
    }
    float bb = b1[t];
    __syncthreads();
    float* bufs = (float*)buf4;
#pragma unroll
    for (int r = 0; r < 16; r++) {
        float v = acc[r] + bb;
        bufs[r * 256 + t] = v > 0.f ? v : (__expf(v) - 1.f);
    }
    __syncthreads();
    int r2 = t >> 4, c2 = t & 15;
    int gr2 = row0 + r2;
    float a = 0.f;
    const float* hrow = bufs + r2 * 256;
#pragma unroll 8
    for (int k = 0; k < FOUT; k++) a += hrow[k] * W2s[k * NC + c2];
    if (gr2 < NN) g_xh2h[gr2 * 16 + c2] = __float2half(a);
    xs2[r2][c2] = a;
    __syncthreads();
    if (c2 < 2 && gr2 < NN) {
        float s = 0.f;
#pragma unroll
        for (int j = 0; j < NC; j++) s += xs2[r2][j] * (c2 ? a2d[j] : a2s[j]);
        if (c2) g_a_dst2[gr2] = s; else g_a_src2[gr2] = s;
    }
}

// ---------------- layer 2 aggregation (plain exp) + log_softmax -----------
__global__ void k_agg2(const float* __restrict__ b2, float* __restrict__ out) {
    int warp = (blockIdx.x * blockDim.x + threadIdx.x) >> 5;
    int lane = threadIdx.x & 31;
    if (warp >= NN) return;
    int d = warp;
    int beg = g_rowptr[d], end = g_rowptr[d + 1];
    float adn = g_a_dst2[d];

    float ssum = 0.f;
    float acc[NC];
#pragma unroll
    for (int j = 0; j < NC; j++) acc[j] = 0.f;

    for (int k = beg + lane; k < end; k += 32) {
        int s = g_col[k];
        float p = __expf(lrelu(g_a_src2[s] + adn));
        ssum += p;
        const uint4* xp = (const uint4*)(g_xh2h + s * 16);  // 32B row = 2×uint4
        uint4 v0 = xp[0];
        uint4 v1 = xp[1];
        __half2* h0 = (__half2*)&v0;
        __half2* h1 = (__half2*)&v1;
#pragma unroll
        for (int j = 0; j < 4; j++) {
            float2 f = __half22float2(h0[j]);
            acc[2 * j]     += f.x * p;
            acc[2 * j + 1] += f.y * p;
        }
#pragma unroll
        for (int j = 0; j < 4; j++) {
            float2 f = __half22float2(h1[j]);
            acc[8 + 2 * j]     += f.x * p;
            acc[8 + 2 * j + 1] += f.y * p;
        }
    }
    ssum = wsum(ssum);
#pragma unroll
    for (int j = 0; j < NC; j++) acc[j] = wsum(acc[j]);
    float inv = 1.f / (ssum + 1e-16f);

    float l[NC];
    float mm = -1e30f;
#pragma unroll
    for (int j = 0; j < NC; j++) { l[j] = acc[j] * inv + b2[j]; mm = fmaxf(mm, l[j]); }
    float ls = 0.f;
#pragma unroll
    for (int j = 0; j < NC; j++) ls += __expf(l[j] - mm);
    ls = logf(ls) + mm;
    float v = l[0];
#pragma unroll
    for (int j = 1; j < NC; j++) if (lane == j) v = l[j];
    if (lane < NC) out[d * NC + lane] = v - ls;
}

// ---------------- launch ---------------------------------------------------
extern "C" void kernel_launch(void* const* d_in, const int* in_sizes, int n_in,
                              void* d_out, int out_size) {
    const float* x   = (const float*)d_in[0];
    const void*  ei  = d_in[1];
    const float* W1  = (const float*)d_in[2];
    const float* as1 = (const float*)d_in[3];
    const float* ad1 = (const float*)d_in[4];
    const float* b1  = (const float*)d_in[5];
    const float* W2  = (const float*)d_in[6];
    const float* as2 = (const float*)d_in[7];
    const float* ad2 = (const float*)d_in[8];
    const float* b2  = (const float*)d_in[9];
    float* out = (float*)d_out;

    static cudaStream_t s2 = nullptr;
    static cudaEvent_t evFork = nullptr, evJoin = nullptr;
    if (!s2) {
        cudaStreamCreateWithFlags(&s2, cudaStreamNonBlocking);
        cudaEventCreateWithFlags(&evFork, cudaEventDisableTiming);
        cudaEventCreateWithFlags(&evJoin, cudaEventDisableTiming);
    }

    // fork: independent weight/attention-scalar chain on s2
    cudaEventRecord(evFork, 0);
    cudaStreamWaitEvent(s2, evFork, 0);
    k_wvec <<<1, 256, 0, s2>>>(W1, as1, ad1);
    k_attsc<<<(NN + 7) / 8, 256, 0, s2>>>(x);
    cudaEventRecord(evJoin, s2);

    // main chain: CSR build
    k_zero <<<(NN + 255) / 256, 256>>>((const long long*)ei);
    k_count<<<(EP + 255) / 256, 256>>>(ei);
    k_scan1<<<SCAN_NB, SCAN_B>>>();
    k_scan3<<<SCAN_NB, SCAN_B>>>();
    k_fill <<<(EP + 255) / 256, 256>>>(ei);

    // join, then fused edge phase + tail
    cudaStreamWaitEvent(0, evJoin, 0);
    k_l1edge <<<(NN + 7) / 8, 256>>>();
    k_l2fused<<<(NN + 15) / 16, 256>>>(W1, b1, W2, as2, ad2);
    k_agg2   <<<(NN + 7) / 8, 256>>>(b2, out);
}